// round 6
// baseline (speedup 1.0000x reference)
#include <cuda_runtime.h>
#include <cstdint>

#define RADIUS 5
#define KS 11
#define IMG_H 256
#define IMG_W 256
#define HW (IMG_H * IMG_W)
#define BX 16
#define BYT 2            // ty; each thread owns output rows 2ty, 2ty+1
#define TZ 4             // window split: 3 rows per tz
#define OUTY 4           // output rows per block
#define TX 26            // halo width (16 + 10)
#define TYR 14           // halo height (4 + 10)
#define PLANE (TYR * TX) // 364
// per-pixel smem: G0(16) G1(16) P1(16) P2(16) P3(4) = 68 B
#define SMEM_BYTES (PLANE * 68)
#define OFF_G1 (16 * PLANE)
#define OFF_P1 (32 * PLANE)
#define OFF_P2 (48 * PLANE)
#define OFF_P3 (64 * PLANE)

// ---------------------------------------------------------------------------
// packed f32x2 helpers (used ONLY for the 8-channel bilateral chain)
// ---------------------------------------------------------------------------
__device__ __forceinline__ uint64_t pk2(float lo, float hi) {
    uint64_t r; asm("mov.b64 %0, {%1,%2};" : "=l"(r) : "f"(lo), "f"(hi)); return r;
}
__device__ __forceinline__ void unpk2(float& lo, float& hi, uint64_t v) {
    asm("mov.b64 {%0,%1}, %2;" : "=f"(lo), "=f"(hi) : "l"(v));
}
__device__ __forceinline__ uint64_t add2(uint64_t a, uint64_t b) {
    uint64_t d; asm("add.rn.f32x2 %0,%1,%2;" : "=l"(d) : "l"(a), "l"(b)); return d;
}
__device__ __forceinline__ uint64_t mul2(uint64_t a, uint64_t b) {
    uint64_t d; asm("mul.rn.f32x2 %0,%1,%2;" : "=l"(d) : "l"(a), "l"(b)); return d;
}
__device__ __forceinline__ uint64_t fma2(uint64_t a, uint64_t b, uint64_t c) {
    uint64_t d; asm("fma.rn.f32x2 %0,%1,%2,%3;" : "=l"(d) : "l"(a), "l"(b), "l"(c)); return d;
}

// ---------------------------------------------------------------------------
// f32 ndtri replicating jax.scipy.special.ndtri (cephes, no FMA contraction).
// ---------------------------------------------------------------------------
template <int N>
__device__ __forceinline__ float polevl_f(float x, const float (&c)[N]) {
    float r = c[0];
#pragma unroll
    for (int i = 1; i < N; ++i) r = __fadd_rn(__fmul_rn(r, x), c[i]);
    return r;
}

__device__ float ndtri_f32(float p) {
    const float P0[5] = {-5.99633501014107895267e1f, 9.80010754185999661536e1f,
                         -5.66762857469070293439e1f, 1.39312609387279679503e1f,
                         -1.23916583867381258016e0f};
    const float Q0[9] = {1.0f, 1.95448858338141759834e0f, 4.67627912898881538453e0f,
                         8.63602421390890590575e1f, -2.25462687854119370527e2f,
                         2.00260212380060660359e2f, -8.20372256168538034246e1f,
                         1.59056225126211695515e1f, -1.18331621121330003142e0f};
    const float P1c[9] = {4.05544892305962419923e0f, 3.15251094599893866154e1f,
                          5.71628192246421288162e1f, 4.40805073893200834700e1f,
                          1.46849561928858024014e1f, 2.18663306850790267539e0f,
                          -1.40256079171354495875e-1f, -3.50424626827848203418e-2f,
                          -8.57456785154685413611e-4f};
    const float Q1c[9] = {1.0f, 1.57799883256466749731e1f, 4.53907635128879210584e1f,
                          4.13172038254672030440e1f, 1.50425385692907503408e1f,
                          2.50464946208309415979e0f, -1.42182922854787788574e-1f,
                          -3.80806407691578277194e-2f, -9.33259480895457427372e-4f};
    const float P2c[9] = {3.23774891776946035970e0f, 6.91522889068984211695e0f,
                          3.93881025292474443415e0f, 1.33303460815807542389e0f,
                          2.01485389549179081538e-1f, 1.23716634817820021358e-2f,
                          3.01581553508235416007e-4f, 2.65806974686737550832e-6f,
                          6.23974539184983651783e-9f};
    const float Q2c[9] = {1.0f, 6.02427039364742014255e0f, 3.67983563856160859403e0f,
                          1.37702099489081330271e0f, 2.16236993594496635890e-1f,
                          1.34204006088543189037e-2f, 3.28014464682127739104e-4f,
                          2.89247864745380683936e-6f, 6.79019408009981274425e-9f};
    const float one_m_expm2 = 0.86466471676338730811f;
    const float expm2 = 0.13533528323661269189f;

    float mcp = (p > one_m_expm2) ? __fadd_rn(1.0f, -p) : p;
    float san = (mcp <= 0.0f) ? 0.5f : mcp;
    float x;
    if (san > expm2) {
        float w = __fadd_rn(san, -0.5f);
        float ww = __fmul_rn(w, w);
        float r = __fdiv_rn(polevl_f(ww, P0), polevl_f(ww, Q0));
        x = __fadd_rn(w, __fmul_rn(__fmul_rn(w, ww), r));
        x = __fmul_rn(x, -2.50662827463100050242f);
    } else {
        float z = __fsqrt_rn(__fmul_rn(-2.0f, logf(san)));
        float ft = __fadd_rn(z, -__fdiv_rn(logf(z), z));
        float iz = __fdiv_rn(1.0f, z);
        float num, den;
        if (z >= 8.0f) { num = polevl_f(iz, P2c); den = polevl_f(iz, Q2c); }
        else           { num = polevl_f(iz, P1c); den = polevl_f(iz, Q1c); }
        float st = __fdiv_rn(__fdiv_rn(num, den), z);
        x = __fadd_rn(ft, -st);
    }
    return (p > one_m_expm2) ? x : -x;
}

__device__ float compute_gamma(int spp) {
    float z = ndtri_f32(0.9975f);
    double df = (double)(2 * spp - 2);
    float z2 = __fmul_rn(z, z);
    float z3 = __fmul_rn(z, z2);
    float z4 = __fmul_rn(z2, z2);
    float z5 = __fmul_rn(z, z4);
    float z7 = __fmul_rn(z3, z4);
    float g1 = __fdiv_rn(__fadd_rn(z3, z), (float)(4.0 * df));
    float g2 = __fdiv_rn(
        __fadd_rn(__fadd_rn(__fmul_rn(5.0f, z5), __fmul_rn(16.0f, z3)), __fmul_rn(3.0f, z)),
        (float)(96.0 * df * df));
    float g3 = __fdiv_rn(
        __fadd_rn(__fadd_rn(__fadd_rn(__fmul_rn(3.0f, z7), __fmul_rn(19.0f, z5)),
                            __fmul_rn(17.0f, z3)),
                  -__fmul_rn(15.0f, z)),
        (float)(384.0 * df * df * df));
    return __fadd_rn(__fadd_rn(__fadd_rn(z, g1), g2), g3);
}

// ---------------------------------------------------------------------------
// Denoiser: block (16,2,4)=128 thr, grid 1024 (16x64). Each (tx,ty) owns
// output rows 2ty,2ty+1 of a 16x4 tile; tz splits the 12-row span 4-way.
// 8 blocks/SM resident -> occ ~50%, per-SM block balance ~1.01.
// ---------------------------------------------------------------------------
__global__ void __launch_bounds__(128, 8)
denoise_kernel(const float* __restrict__ img, const float* __restrict__ gd,
               const float* __restrict__ est, const float* __restrict__ var,
               const int* __restrict__ spp_p, float* __restrict__ out) {
    extern __shared__ char smraw[];
    float4* G0 = (float4*)smraw;
    float4* G1 = (float4*)(smraw + OFF_G1);
    float4* P1 = (float4*)(smraw + OFF_P1);
    float4* P2 = (float4*)(smraw + OFF_P2);
    float*  P3 = (float*) (smraw + OFF_P3);
    __shared__ float s_g2;

    const int tx = threadIdx.x, ty = threadIdx.y, tz = threadIdx.z;
    const int tid = (tz * BYT + ty) * BX + tx;
    const int gx0 = blockIdx.x * BX - RADIUS;
    const int gy0 = blockIdx.y * OUTY - RADIUS;
    const float NINF = __int_as_float(0xff800000);
    // sqrt(0.5 * sigma_c * log2(e))
    const float SCA = 0.26857906f;   // sigma 0.1
    const float SCB = 6.00561167f;   // sigma 50
    const float SCC = 2.68579063f;   // sigma 10

    for (int i = tid; i < PLANE; i += 128) {
        int ly = i / TX, lx = i - ly * TX;
        int gy = gy0 + ly, gx = gx0 + lx;
        bool inb = ((unsigned)gy < IMG_H) & ((unsigned)gx < IMG_W);
        int g = gy * IMG_W + gx;
        float4 a, b, p1, p2; float p3;
        if (inb) {
            a = make_float4(gd[g] * SCA, gd[HW + g] * SCA,
                            gd[2 * HW + g] * SCB, gd[3 * HW + g] * SCB);
            b = make_float4(gd[4 * HW + g] * SCB, gd[5 * HW + g] * SCC,
                            gd[6 * HW + g] * SCC, gd[7 * HW + g] * SCC);
            float v0 = var[g], v1 = var[HW + g], v2 = var[2 * HW + g];
            v0 = (v0 == 0.f) ? NINF : v0;
            v1 = (v1 == 0.f) ? NINF : v1;
            v2 = (v2 == 0.f) ? NINF : v2;
            p1 = make_float4(est[g], v0, est[HW + g], v1);
            p2 = make_float4(est[2 * HW + g], v2, img[g], img[HW + g]);
            p3 = img[2 * HW + g];
        } else {
            a = make_float4(0.f, 0.f, 0.f, 0.f); b = a;
            p1 = make_float4(0.f, NINF, 0.f, NINF);
            p2 = make_float4(0.f, NINF, 0.f, 0.f);
            p3 = 0.f;
        }
        G0[i] = a; G1[i] = b; P1[i] = p1; P2[i] = p2; P3[i] = p3;
    }
    if (tid == 0) { float gm = compute_gamma(spp_p[0]); s_g2 = gm * gm; }
    __syncthreads();
    const float g2 = s_g2;
    const unsigned sbase = (unsigned)__cvta_generic_to_shared(smraw);

    // Center data for both owned pixels (rows 2ty, 2ty+1).
    const int ci0 = (2 * ty + RADIUS) * TX + tx + RADIUS;
    const int ci1 = ci0 + TX;
    const float4 cga = G0[ci0], cgb = G1[ci0];
    const float4 cha = G0[ci1], chb = G1[ci1];
    const uint64_t n0a = pk2(-cga.x, -cga.y), n0b = pk2(-cga.z, -cga.w);
    const uint64_t n0c = pk2(-cgb.x, -cgb.y), n0d = pk2(-cgb.z, -cgb.w);
    const uint64_t n1a = pk2(-cha.x, -cha.y), n1b = pk2(-cha.z, -cha.w);
    const uint64_t n1c = pk2(-chb.x, -chb.y), n1d = pk2(-chb.z, -chb.w);
    const float4 q10 = P1[ci0], q20 = P2[ci0];
    const float4 q11 = P1[ci1], q21 = P2[ci1];
    const float ce00 = q10.x, cv00 = q10.y, ce01 = q10.z, cv01 = q10.w;
    const float ce02 = q20.x, cv02 = q20.y;
    const float ce10 = q11.x, cv10 = q11.y, ce11 = q11.z, cv11 = q11.w;
    const float ce12 = q21.x, cv12 = q21.y;

    float sw0 = 0.f, a00 = 0.f, a01 = 0.f, a02 = 0.f;
    float sw1 = 0.f, a10 = 0.f, a11 = 0.f, a12 = 0.f;
    const int rstart = tz * 3;

#pragma unroll
    for (int rr = 0; rr < 3; ++rr) {
        const int r = rstart + rr;                  // 0..11 over the 12-row span
        const bool act0 = (r <= 10), act1 = (r >= 1);
        const bool f0 = (r == RADIUS), f1 = (r == RADIUS + 1);
        const int rowb = (2 * ty + r) * TX + tx;
        const unsigned ga = sbase + (unsigned)(rowb * 16);
#pragma unroll
        for (int dx = 0; dx < KS; ++dx) {
            const int ni = rowb + dx;
            uint64_t g01, g23, g45, g67;
            asm("ld.shared.v2.u64 {%0,%1}, [%2];"
                : "=l"(g01), "=l"(g23) : "r"(ga + dx * 16));
            asm("ld.shared.v2.u64 {%0,%1}, [%2];"
                : "=l"(g45), "=l"(g67) : "r"(ga + dx * 16 + OFF_G1));
            // bilateral weight, center 0 (stays in u64 domain end-to-end)
            uint64_t d0a = add2(g01, n0a), d0b = add2(g23, n0b);
            uint64_t d0c = add2(g45, n0c), d0d = add2(g67, n0d);
            uint64_t sA0 = mul2(d0a, d0a), sB0 = mul2(d0b, d0b);
            sA0 = fma2(d0c, d0c, sA0); sB0 = fma2(d0d, d0d, sB0);
            sA0 = add2(sA0, sB0);
            float lo0, hi0; unpk2(lo0, hi0, sA0);
            float bw0; asm("ex2.approx.f32 %0, %1;" : "=f"(bw0) : "f"(-lo0 - hi0));
            // bilateral weight, center 1
            uint64_t d1a = add2(g01, n1a), d1b = add2(g23, n1b);
            uint64_t d1c = add2(g45, n1c), d1d = add2(g67, n1d);
            uint64_t sA1 = mul2(d1a, d1a), sB1 = mul2(d1b, d1b);
            sA1 = fma2(d1c, d1c, sA1); sB1 = fma2(d1d, d1d, sB1);
            sA1 = add2(sA1, sB1);
            float lo1, hi1; unpk2(lo1, hi1, sA1);
            float bw1; asm("ex2.approx.f32 %0, %1;" : "=f"(bw1) : "f"(-lo1 - hi1));

            // membership: plain scalar loads + FFMA, min-reduce, one setp
            const float4 p1 = P1[ni];               // e0,v0,e1,v1
            const float4 p2 = P2[ni];               // e2,v2,i0,i1
            const float i2 = P3[ni];
            float d, r0, r1, r2;
            d = ce00 - p1.x; r0 = fmaf(g2, cv00 + p1.y, -(d * d));
            d = ce01 - p1.z; r1 = fmaf(g2, cv01 + p1.w, -(d * d));
            d = ce02 - p2.x; r2 = fmaf(g2, cv02 + p2.y, -(d * d));
            bool mem0 = fminf(fminf(r0, r1), r2) > 0.f;
            d = ce10 - p1.x; r0 = fmaf(g2, cv10 + p1.y, -(d * d));
            d = ce11 - p1.z; r1 = fmaf(g2, cv11 + p1.w, -(d * d));
            d = ce12 - p2.x; r2 = fmaf(g2, cv12 + p2.y, -(d * d));
            bool mem1 = fminf(fminf(r0, r1), r2) > 0.f;

            if (dx == RADIUS) {                      // force own center pixel in
                mem0 = mem0 | f0;
                mem1 = mem1 | f1;
            }
            mem0 = mem0 & act0;
            mem1 = mem1 & act1;
            float fw0 = mem0 ? bw0 : 0.f;
            float fw1 = mem1 ? bw1 : 0.f;
            sw0 += fw0;
            a00 = fmaf(p2.z, fw0, a00); a01 = fmaf(p2.w, fw0, a01); a02 = fmaf(i2, fw0, a02);
            sw1 += fw1;
            a10 = fmaf(p2.z, fw1, a10); a11 = fmaf(p2.w, fw1, a11); a12 = fmaf(i2, fw1, a12);
        }
    }

    // 4-way tz reduction through smem (reuse staging region; 4 KB).
    __syncthreads();
    float4* R = (float4*)smraw;
    const int pix0 = (2 * ty) * BX + tx;            // 0..63 over the 16x4 tile
    R[tz * 64 + pix0] = make_float4(sw0, a00, a01, a02);
    R[tz * 64 + pix0 + BX] = make_float4(sw1, a10, a11, a12);
    __syncthreads();
    if (tid < 64) {
        float4 u = R[tid], v = R[64 + tid], w = R[128 + tid], x = R[192 + tid];
        float swt = (u.x + v.x) + (w.x + x.x);
        float inv = __fdiv_rn(1.0f, fmaxf(swt, 1e-10f));
        int ox = blockIdx.x * BX + (tid & 15);
        int oy = blockIdx.y * OUTY + (tid >> 4);
        int o = oy * IMG_W + ox;
        out[o] = ((u.y + v.y) + (w.y + x.y)) * inv;
        out[HW + o] = ((u.z + v.z) + (w.z + x.z)) * inv;
        out[2 * HW + o] = ((u.w + v.w) + (w.w + x.w)) * inv;
    }
}

extern "C" void kernel_launch(void* const* d_in, const int* in_sizes, int n_in,
                              void* d_out, int out_size) {
    const float* img = (const float*)d_in[0];
    const float* gd  = (const float*)d_in[1];
    const float* est = (const float*)d_in[2];
    const float* var = (const float*)d_in[3];
    const int*   spp = (const int*)d_in[4];
    float* out = (float*)d_out;

    dim3 block(BX, BYT, TZ);
    dim3 grid(IMG_W / BX, IMG_H / OUTY);
    denoise_kernel<<<grid, block, SMEM_BYTES>>>(img, gd, est, var, spp, out);
}

// round 7
// speedup vs baseline: 1.0014x; 1.0014x over previous
#include <cuda_runtime.h>
#include <cstdint>

#define RADIUS 5
#define KS 11
#define IMG_H 256
#define IMG_W 256
#define HW (IMG_H * IMG_W)
#define BX 32
#define BYT 2            // ty; each thread owns output rows 2ty, 2ty+1
#define TZ 4             // window split: 3 rows per tz
#define OUTY 4           // output rows per block
#define TX 42            // halo width (32 + 10)
#define TYR 14           // halo height (4 + 10)
#define PLANE (TYR * TX) // 588
// per-pixel smem: G0(16) G1(16) P1(16) P2(16) P3(4) = 68 B
#define SMEM_BYTES (PLANE * 68)
#define OFF_G1 (16 * PLANE)
#define OFF_P1 (32 * PLANE)
#define OFF_P2 (48 * PLANE)
#define OFF_P3 (64 * PLANE)

// ---------------------------------------------------------------------------
// packed f32x2 helpers (used ONLY for the 8-channel bilateral chain)
// ---------------------------------------------------------------------------
__device__ __forceinline__ uint64_t pk2(float lo, float hi) {
    uint64_t r; asm("mov.b64 %0, {%1,%2};" : "=l"(r) : "f"(lo), "f"(hi)); return r;
}
__device__ __forceinline__ void unpk2(float& lo, float& hi, uint64_t v) {
    asm("mov.b64 {%0,%1}, %2;" : "=f"(lo), "=f"(hi) : "l"(v));
}
__device__ __forceinline__ uint64_t add2(uint64_t a, uint64_t b) {
    uint64_t d; asm("add.rn.f32x2 %0,%1,%2;" : "=l"(d) : "l"(a), "l"(b)); return d;
}
__device__ __forceinline__ uint64_t mul2(uint64_t a, uint64_t b) {
    uint64_t d; asm("mul.rn.f32x2 %0,%1,%2;" : "=l"(d) : "l"(a), "l"(b)); return d;
}
__device__ __forceinline__ uint64_t fma2(uint64_t a, uint64_t b, uint64_t c) {
    uint64_t d; asm("fma.rn.f32x2 %0,%1,%2,%3;" : "=l"(d) : "l"(a), "l"(b), "l"(c)); return d;
}

// ---------------------------------------------------------------------------
// f32 ndtri replicating jax.scipy.special.ndtri (cephes, no FMA contraction).
// ---------------------------------------------------------------------------
template <int N>
__device__ __forceinline__ float polevl_f(float x, const float (&c)[N]) {
    float r = c[0];
#pragma unroll
    for (int i = 1; i < N; ++i) r = __fadd_rn(__fmul_rn(r, x), c[i]);
    return r;
}

__device__ float ndtri_f32(float p) {
    const float P0[5] = {-5.99633501014107895267e1f, 9.80010754185999661536e1f,
                         -5.66762857469070293439e1f, 1.39312609387279679503e1f,
                         -1.23916583867381258016e0f};
    const float Q0[9] = {1.0f, 1.95448858338141759834e0f, 4.67627912898881538453e0f,
                         8.63602421390890590575e1f, -2.25462687854119370527e2f,
                         2.00260212380060660359e2f, -8.20372256168538034246e1f,
                         1.59056225126211695515e1f, -1.18331621121330003142e0f};
    const float P1c[9] = {4.05544892305962419923e0f, 3.15251094599893866154e1f,
                          5.71628192246421288162e1f, 4.40805073893200834700e1f,
                          1.46849561928858024014e1f, 2.18663306850790267539e0f,
                          -1.40256079171354495875e-1f, -3.50424626827848203418e-2f,
                          -8.57456785154685413611e-4f};
    const float Q1c[9] = {1.0f, 1.57799883256466749731e1f, 4.53907635128879210584e1f,
                          4.13172038254672030440e1f, 1.50425385692907503408e1f,
                          2.50464946208309415979e0f, -1.42182922854787788574e-1f,
                          -3.80806407691578277194e-2f, -9.33259480895457427372e-4f};
    const float P2c[9] = {3.23774891776946035970e0f, 6.91522889068984211695e0f,
                          3.93881025292474443415e0f, 1.33303460815807542389e0f,
                          2.01485389549179081538e-1f, 1.23716634817820021358e-2f,
                          3.01581553508235416007e-4f, 2.65806974686737550832e-6f,
                          6.23974539184983651783e-9f};
    const float Q2c[9] = {1.0f, 6.02427039364742014255e0f, 3.67983563856160859403e0f,
                          1.37702099489081330271e0f, 2.16236993594496635890e-1f,
                          1.34204006088543189037e-2f, 3.28014464682127739104e-4f,
                          2.89247864745380683936e-6f, 6.79019408009981274425e-9f};
    const float one_m_expm2 = 0.86466471676338730811f;
    const float expm2 = 0.13533528323661269189f;

    float mcp = (p > one_m_expm2) ? __fadd_rn(1.0f, -p) : p;
    float san = (mcp <= 0.0f) ? 0.5f : mcp;
    float x;
    if (san > expm2) {
        float w = __fadd_rn(san, -0.5f);
        float ww = __fmul_rn(w, w);
        float r = __fdiv_rn(polevl_f(ww, P0), polevl_f(ww, Q0));
        x = __fadd_rn(w, __fmul_rn(__fmul_rn(w, ww), r));
        x = __fmul_rn(x, -2.50662827463100050242f);
    } else {
        float z = __fsqrt_rn(__fmul_rn(-2.0f, logf(san)));
        float ft = __fadd_rn(z, -__fdiv_rn(logf(z), z));
        float iz = __fdiv_rn(1.0f, z);
        float num, den;
        if (z >= 8.0f) { num = polevl_f(iz, P2c); den = polevl_f(iz, Q2c); }
        else           { num = polevl_f(iz, P1c); den = polevl_f(iz, Q1c); }
        float st = __fdiv_rn(__fdiv_rn(num, den), z);
        x = __fadd_rn(ft, -st);
    }
    return (p > one_m_expm2) ? x : -x;
}

__device__ float compute_gamma(int spp) {
    float z = ndtri_f32(0.9975f);
    double df = (double)(2 * spp - 2);
    float z2 = __fmul_rn(z, z);
    float z3 = __fmul_rn(z, z2);
    float z4 = __fmul_rn(z2, z2);
    float z5 = __fmul_rn(z, z4);
    float z7 = __fmul_rn(z3, z4);
    float g1 = __fdiv_rn(__fadd_rn(z3, z), (float)(4.0 * df));
    float g2 = __fdiv_rn(
        __fadd_rn(__fadd_rn(__fmul_rn(5.0f, z5), __fmul_rn(16.0f, z3)), __fmul_rn(3.0f, z)),
        (float)(96.0 * df * df));
    float g3 = __fdiv_rn(
        __fadd_rn(__fadd_rn(__fadd_rn(__fmul_rn(3.0f, z7), __fmul_rn(19.0f, z5)),
                            __fmul_rn(17.0f, z3)),
                  -__fmul_rn(15.0f, z)),
        (float)(384.0 * df * df * df));
    return __fadd_rn(__fadd_rn(__fadd_rn(z, g1), g2), g3);
}

// ---------------------------------------------------------------------------
// Denoiser: block (32,2,4)=256 thr, 512 blocks, 32x4 output tile.
// Each (tx,ty) owns output rows 2ty,2ty+1; tz splits the 12-row span 4-way.
// launch_bounds(256,2): up to 128 regs -> NO SPILLS (the round 4-6 binder).
// ---------------------------------------------------------------------------
__global__ void __launch_bounds__(256, 2)
denoise_kernel(const float* __restrict__ img, const float* __restrict__ gd,
               const float* __restrict__ est, const float* __restrict__ var,
               const int* __restrict__ spp_p, float* __restrict__ out) {
    extern __shared__ char smraw[];
    float4* G0 = (float4*)smraw;
    float4* G1 = (float4*)(smraw + OFF_G1);
    float4* P1 = (float4*)(smraw + OFF_P1);
    float4* P2 = (float4*)(smraw + OFF_P2);
    float*  P3 = (float*) (smraw + OFF_P3);
    __shared__ float s_g2;

    const int tx = threadIdx.x, ty = threadIdx.y, tz = threadIdx.z;
    const int tid = (tz * BYT + ty) * BX + tx;
    const int gx0 = blockIdx.x * BX - RADIUS;
    const int gy0 = blockIdx.y * OUTY - RADIUS;
    const float NINF = __int_as_float(0xff800000);
    // sqrt(0.5 * sigma_c * log2(e))
    const float SCA = 0.26857906f;   // sigma 0.1
    const float SCB = 6.00561167f;   // sigma 50
    const float SCC = 2.68579063f;   // sigma 10

    for (int i = tid; i < PLANE; i += 256) {
        int ly = i / TX, lx = i - ly * TX;
        int gy = gy0 + ly, gx = gx0 + lx;
        bool inb = ((unsigned)gy < IMG_H) & ((unsigned)gx < IMG_W);
        int g = gy * IMG_W + gx;
        float4 a, b, p1, p2; float p3;
        if (inb) {
            a = make_float4(gd[g] * SCA, gd[HW + g] * SCA,
                            gd[2 * HW + g] * SCB, gd[3 * HW + g] * SCB);
            b = make_float4(gd[4 * HW + g] * SCB, gd[5 * HW + g] * SCC,
                            gd[6 * HW + g] * SCC, gd[7 * HW + g] * SCC);
            float v0 = var[g], v1 = var[HW + g], v2 = var[2 * HW + g];
            v0 = (v0 == 0.f) ? NINF : v0;
            v1 = (v1 == 0.f) ? NINF : v1;
            v2 = (v2 == 0.f) ? NINF : v2;
            p1 = make_float4(est[g], v0, est[HW + g], v1);
            p2 = make_float4(est[2 * HW + g], v2, img[g], img[HW + g]);
            p3 = img[2 * HW + g];
        } else {
            a = make_float4(0.f, 0.f, 0.f, 0.f); b = a;
            p1 = make_float4(0.f, NINF, 0.f, NINF);
            p2 = make_float4(0.f, NINF, 0.f, 0.f);
            p3 = 0.f;
        }
        G0[i] = a; G1[i] = b; P1[i] = p1; P2[i] = p2; P3[i] = p3;
    }
    if (tid == 0) { float gm = compute_gamma(spp_p[0]); s_g2 = gm * gm; }
    __syncthreads();
    const float g2 = s_g2;
    const unsigned sbase = (unsigned)__cvta_generic_to_shared(smraw);

    // Center data for both owned pixels (rows 2ty, 2ty+1).
    const int ci0 = (2 * ty + RADIUS) * TX + tx + RADIUS;
    const int ci1 = ci0 + TX;
    const float4 cga = G0[ci0], cgb = G1[ci0];
    const float4 cha = G0[ci1], chb = G1[ci1];
    const uint64_t n0a = pk2(-cga.x, -cga.y), n0b = pk2(-cga.z, -cga.w);
    const uint64_t n0c = pk2(-cgb.x, -cgb.y), n0d = pk2(-cgb.z, -cgb.w);
    const uint64_t n1a = pk2(-cha.x, -cha.y), n1b = pk2(-cha.z, -cha.w);
    const uint64_t n1c = pk2(-chb.x, -chb.y), n1d = pk2(-chb.z, -chb.w);
    const float4 q10 = P1[ci0], q20 = P2[ci0];
    const float4 q11 = P1[ci1], q21 = P2[ci1];
    const float ce00 = q10.x, cv00 = q10.y, ce01 = q10.z, cv01 = q10.w;
    const float ce02 = q20.x, cv02 = q20.y;
    const float ce10 = q11.x, cv10 = q11.y, ce11 = q11.z, cv11 = q11.w;
    const float ce12 = q21.x, cv12 = q21.y;

    float sw0 = 0.f, a00 = 0.f, a01 = 0.f, a02 = 0.f;
    float sw1 = 0.f, a10 = 0.f, a11 = 0.f, a12 = 0.f;
    const int rstart = tz * 3;

#pragma unroll
    for (int rr = 0; rr < 3; ++rr) {
        const int r = rstart + rr;                  // 0..11 over the 12-row span
        const bool act0 = (r <= 10), act1 = (r >= 1);
        const bool f0 = (r == RADIUS), f1 = (r == RADIUS + 1);
        const int rowb = (2 * ty + r) * TX + tx;
        const unsigned ga = sbase + (unsigned)(rowb * 16);
#pragma unroll
        for (int dx = 0; dx < KS; ++dx) {
            const int ni = rowb + dx;
            uint64_t g01, g23, g45, g67;
            asm("ld.shared.v2.u64 {%0,%1}, [%2];"
                : "=l"(g01), "=l"(g23) : "r"(ga + dx * 16));
            asm("ld.shared.v2.u64 {%0,%1}, [%2];"
                : "=l"(g45), "=l"(g67) : "r"(ga + dx * 16 + OFF_G1));
            // bilateral weight, center 0 (u64 domain end-to-end)
            uint64_t d0a = add2(g01, n0a), d0b = add2(g23, n0b);
            uint64_t d0c = add2(g45, n0c), d0d = add2(g67, n0d);
            uint64_t sA0 = mul2(d0a, d0a), sB0 = mul2(d0b, d0b);
            sA0 = fma2(d0c, d0c, sA0); sB0 = fma2(d0d, d0d, sB0);
            sA0 = add2(sA0, sB0);
            float lo0, hi0; unpk2(lo0, hi0, sA0);
            float bw0; asm("ex2.approx.f32 %0, %1;" : "=f"(bw0) : "f"(-lo0 - hi0));
            // bilateral weight, center 1
            uint64_t d1a = add2(g01, n1a), d1b = add2(g23, n1b);
            uint64_t d1c = add2(g45, n1c), d1d = add2(g67, n1d);
            uint64_t sA1 = mul2(d1a, d1a), sB1 = mul2(d1b, d1b);
            sA1 = fma2(d1c, d1c, sA1); sB1 = fma2(d1d, d1d, sB1);
            sA1 = add2(sA1, sB1);
            float lo1, hi1; unpk2(lo1, hi1, sA1);
            float bw1; asm("ex2.approx.f32 %0, %1;" : "=f"(bw1) : "f"(-lo1 - hi1));

            // membership: scalar FFMA + min-reduce (poison -inf flows through)
            const float4 p1 = P1[ni];               // e0,v0,e1,v1
            const float4 p2 = P2[ni];               // e2,v2,i0,i1
            const float i2 = P3[ni];
            float d, r0, r1, r2;
            d = ce00 - p1.x; r0 = fmaf(g2, cv00 + p1.y, -(d * d));
            d = ce01 - p1.z; r1 = fmaf(g2, cv01 + p1.w, -(d * d));
            d = ce02 - p2.x; r2 = fmaf(g2, cv02 + p2.y, -(d * d));
            bool mem0 = fminf(fminf(r0, r1), r2) > 0.f;
            d = ce10 - p1.x; r0 = fmaf(g2, cv10 + p1.y, -(d * d));
            d = ce11 - p1.z; r1 = fmaf(g2, cv11 + p1.w, -(d * d));
            d = ce12 - p2.x; r2 = fmaf(g2, cv12 + p2.y, -(d * d));
            bool mem1 = fminf(fminf(r0, r1), r2) > 0.f;

            if (dx == RADIUS) {                      // force own center pixel in
                mem0 = mem0 | f0;
                mem1 = mem1 | f1;
            }
            mem0 = mem0 & act0;
            mem1 = mem1 & act1;
            float fw0 = mem0 ? bw0 : 0.f;
            float fw1 = mem1 ? bw1 : 0.f;
            sw0 += fw0;
            a00 = fmaf(p2.z, fw0, a00); a01 = fmaf(p2.w, fw0, a01); a02 = fmaf(i2, fw0, a02);
            sw1 += fw1;
            a10 = fmaf(p2.z, fw1, a10); a11 = fmaf(p2.w, fw1, a11); a12 = fmaf(i2, fw1, a12);
        }
    }

    // 4-way tz reduction through smem (conflict-free layout R[tz*128 + pix]).
    __syncthreads();
    float4* R = (float4*)smraw;
    const int pix0 = (2 * ty) * BX + tx;
    R[tz * 128 + pix0] = make_float4(sw0, a00, a01, a02);
    R[tz * 128 + pix0 + BX] = make_float4(sw1, a10, a11, a12);
    __syncthreads();
    if (tid < 128) {
        float4 u = R[tid], v = R[128 + tid], w = R[256 + tid], x = R[384 + tid];
        float swt = (u.x + v.x) + (w.x + x.x);
        float inv = __fdiv_rn(1.0f, fmaxf(swt, 1e-10f));
        int ox = blockIdx.x * BX + (tid & 31);
        int oy = blockIdx.y * OUTY + (tid >> 5);
        int o = oy * IMG_W + ox;
        out[o] = ((u.y + v.y) + (w.y + x.y)) * inv;
        out[HW + o] = ((u.z + v.z) + (w.z + x.z)) * inv;
        out[2 * HW + o] = ((u.w + v.w) + (w.w + x.w)) * inv;
    }
}

extern "C" void kernel_launch(void* const* d_in, const int* in_sizes, int n_in,
                              void* d_out, int out_size) {
    const float* img = (const float*)d_in[0];
    const float* gd  = (const float*)d_in[1];
    const float* est = (const float*)d_in[2];
    const float* var = (const float*)d_in[3];
    const int*   spp = (const int*)d_in[4];
    float* out = (float*)d_out;

    dim3 block(BX, BYT, TZ);
    dim3 grid(IMG_W / BX, IMG_H / OUTY);
    denoise_kernel<<<grid, block, SMEM_BYTES>>>(img, gd, est, var, spp, out);
}